// round 6
// baseline (speedup 1.0000x reference)
#include <cuda_runtime.h>

// ============================================================================
// Compile-time real Clebsch-Gordan coefficients (constexpr port of reference)
// ============================================================================

__host__ __device__ constexpr double cfact(int n) {
    double r = 1.0;
    for (int k = 2; k <= n; ++k) r *= (double)k;
    return r;
}

__host__ __device__ constexpr double csqrt(double x) {
    if (x <= 0.0) return 0.0;
    double g = x > 1.0 ? x : 1.0;
    for (int it = 0; it < 100; ++it) g = 0.5 * (g + x / g);
    return g;
}

__host__ __device__ constexpr int imax3(int a, int b, int c) { int m = a; if (b > m) m = b; if (c > m) m = c; return m; }
__host__ __device__ constexpr int imin3(int a, int b, int c) { int m = a; if (b < m) m = b; if (c < m) m = c; return m; }
__host__ __device__ constexpr int iabs_(int a) { return a < 0 ? -a : a; }
__host__ __device__ constexpr double dabs_(double a) { return a < 0.0 ? -a : a; }

// Complex Clebsch-Gordan <l1 m1 l2 m2 | l3 m3> via Racah formula
__host__ __device__ constexpr double cg_complex(int l1, int m1, int l2, int m2, int l3, int m3) {
    if (m1 + m2 != m3 || l3 < iabs_(l1 - l2) || l3 > l1 + l2) return 0.0;
    double pre = csqrt((double)(2 * l3 + 1) * cfact(l1 + l2 - l3) * cfact(l1 - l2 + l3) *
                       cfact(-l1 + l2 + l3) / cfact(l1 + l2 + l3 + 1));
    pre *= csqrt(cfact(l1 + m1) * cfact(l1 - m1) * cfact(l2 + m2) * cfact(l2 - m2) *
                 cfact(l3 + m3) * cfact(l3 - m3));
    int kmin = imax3(0, l2 - l3 - m1, l1 - l3 + m2);
    int kmax = imin3(l1 + l2 - l3, l1 - m1, l2 + m2);
    double s = 0.0;
    for (int k = kmin; k <= kmax; ++k) {
        double d = cfact(k) * cfact(l1 + l2 - l3 - k) * cfact(l1 - m1 - k) *
                   cfact(l2 + m2 - k) * cfact(l3 - l2 + m1 + k) * cfact(l3 - l1 - m2 + k);
        s += ((k & 1) ? -1.0 : 1.0) / d;
    }
    return pre * s;
}

template <int L1, int L2, int L3>
struct CGT {
    double v[2 * L1 + 1][2 * L2 + 1][2 * L3 + 1];
};

// Real-basis CG tensor (exact port of reference: .imag if it dominates, else .real)
template <int L1, int L2, int L3>
__host__ __device__ constexpr CGT<L1, L2, L3> make_cg() {
    constexpr int NA = 2 * L1 + 1, NB = 2 * L2 + 1, NC = 2 * L3 + 1;
    const double is2 = 1.0 / csqrt(2.0);

    double Ur[3][7][7] = {};
    double Ui[3][7][7] = {};
    int Ls[3] = {L1, L2, L3};
    for (int t = 0; t < 3; ++t) {
        int l = Ls[t];
        for (int mp = -l; mp <= l; ++mp) {
            int r = mp + l;
            if (mp > 0) {
                Ur[t][r][mp + l]  = ((mp & 1) ? -1.0 : 1.0) * is2;
                Ur[t][r][-mp + l] = is2;
            } else if (mp == 0) {
                Ur[t][r][l] = 1.0;
            } else {
                Ui[t][r][mp + l]  = is2;
                Ui[t][r][-mp + l] = -(((-mp) & 1) ? -1.0 : 1.0) * is2;
            }
        }
    }

    double Cc[7][7][7] = {};
    for (int m = 0; m < NA; ++m)
        for (int n = 0; n < NB; ++n)
            for (int o = 0; o < NC; ++o)
                Cc[m][n][o] = cg_complex(L1, m - L1, L2, n - L2, L3, o - L3);

    double Tre[NA][NB][NC] = {};
    double Tim[NA][NB][NC] = {};
    double maxre = 0.0, maxim = 0.0;
    for (int a = 0; a < NA; ++a)
        for (int b = 0; b < NB; ++b)
            for (int c = 0; c < NC; ++c) {
                double are = 0.0, aim = 0.0;
                for (int m = 0; m < NA; ++m)
                    for (int n = 0; n < NB; ++n) {
                        int o = (m - L1) + (n - L2) + L3;
                        if (o < 0 || o >= NC) continue;
                        double cc = Cc[m][n][o];
                        if (cc == 0.0) continue;
                        double xr = Ur[0][a][m], xi = Ui[0][a][m];
                        double yr = Ur[1][b][n], yi = Ui[1][b][n];
                        double zr = Ur[2][c][o], zi = -Ui[2][c][o];
                        double pr = xr * yr - xi * yi;
                        double pi = xr * yi + xi * yr;
                        double tr = pr * zr - pi * zi;
                        double ti = pr * zi + pi * zr;
                        are += tr * cc;
                        aim += ti * cc;
                    }
                Tre[a][b][c] = are;
                Tim[a][b][c] = aim;
                if (dabs_(are) > maxre) maxre = dabs_(are);
                if (dabs_(aim) > maxim) maxim = dabs_(aim);
            }

    CGT<L1, L2, L3> R = {};
    bool useim = maxim > maxre;
    for (int a = 0; a < NA; ++a)
        for (int b = 0; b < NB; ++b)
            for (int c = 0; c < NC; ++c)
                R.v[a][b][c] = useim ? Tim[a][b][c] : Tre[a][b][c];
    return R;
}

// Exchange sign sigma s.t. T(L2,L1,L3)[b][a][c] == sigma * T(L1,L2,L3)[a][b][c]
template <int L1, int L2, int L3>
__host__ __device__ constexpr double exch_sign() {
    CGT<L1, L2, L3> A = make_cg<L1, L2, L3>();
    CGT<L2, L1, L3> B = make_cg<L2, L1, L3>();
    for (int a = 0; a < 2 * L1 + 1; ++a)
        for (int b = 0; b < 2 * L2 + 1; ++b)
            for (int c = 0; c < 2 * L3 + 1; ++c)
                if (dabs_(A.v[a][b][c]) > 1e-9)
                    return B.v[b][a][c] / A.v[a][b][c];
    return 0.0;
}

// Does the symmetrized (self-coupling) tensor have any nonzero?
template <int L, int L3>
__host__ __device__ constexpr bool sym_any() {
    CGT<L, L, L3> T = make_cg<L, L, L3>();
    for (int a = 0; a < 2 * L + 1; ++a)
        for (int b = a; b < 2 * L + 1; ++b)
            for (int c = 0; c < 2 * L3 + 1; ++c) {
                double w = (a == b) ? T.v[a][b][c] : (T.v[a][b][c] + T.v[b][a][c]);
                if (dabs_(w) > 1e-12) return true;
            }
    return false;
}

// ============================================================================
// Contractions. CG weights are compile-time constants; ~zero terms are DCE'd,
// surviving terms become FFMA with immediate multipliers.
// ============================================================================

template <int L1, int L2, int L3>
__device__ __forceinline__ void acc_path(float scale, const float* u, const float* v, float* o) {
    constexpr CGT<L1, L2, L3> T = make_cg<L1, L2, L3>();
    float tmp[2 * L3 + 1];
#pragma unroll
    for (int c = 0; c < 2 * L3 + 1; ++c) tmp[c] = 0.0f;
#pragma unroll
    for (int a = 0; a < 2 * L1 + 1; ++a) {
#pragma unroll
        for (int b = 0; b < 2 * L2 + 1; ++b) {
            float p = u[a] * v[b];
#pragma unroll
            for (int c = 0; c < 2 * L3 + 1; ++c) {
                constexpr double EPS = 1e-12;
                double wd = T.v[a][b][c];
                if (wd > EPS || wd < -EPS) tmp[c] = fmaf((float)wd, p, tmp[c]);
            }
        }
    }
#pragma unroll
    for (int c = 0; c < 2 * L3 + 1; ++c) o[c] = fmaf(scale, tmp[c], o[c]);
}

// Self-coupling, symmetrized over (a,b): products only for a<=b; fully
// antisymmetric paths drop at compile time.
template <int L, int L3>
__device__ __forceinline__ void acc_sym(float scale, const float* u, float* o) {
    if constexpr (!sym_any<L, L3>()) return;
    constexpr CGT<L, L, L3> T = make_cg<L, L, L3>();
    float tmp[2 * L3 + 1];
#pragma unroll
    for (int c = 0; c < 2 * L3 + 1; ++c) tmp[c] = 0.0f;
#pragma unroll
    for (int a = 0; a < 2 * L + 1; ++a) {
#pragma unroll
        for (int b = a; b < 2 * L + 1; ++b) {
            float p = u[a] * u[b];
#pragma unroll
            for (int c = 0; c < 2 * L3 + 1; ++c) {
                constexpr double EPS = 1e-12;
                double wd = (a == b) ? T.v[a][b][c] : (T.v[a][b][c] + T.v[b][a][c]);
                if (wd > EPS || wd < -EPS) tmp[c] = fmaf((float)wd, p, tmp[c]);
            }
        }
    }
#pragma unroll
    for (int c = 0; c < 2 * L3 + 1; ++c) o[c] = fmaf(scale, tmp[c], o[c]);
}

// ============================================================================
// Kernel. Layout facts (METADATA=[64,48,32], MAX_L=3):
//   OFF_IN = {0,64,208}, DIM_IN=368; OFF_OUT={0,64,208,448}, DIM_OUT=672
//   (MD_OV={64,48,48,32}: l2 out block has 48 channels; 32..47 fed only by
//    path (1,1,2); keep-l2 covers channels 0..31 only)
//   mix base offsets (PATHS order):
//     (0,0,0):0 (0,1,1):64 (0,2,2):112 (1,0,1):144 (1,1,0):192 (1,1,1):240
//     (1,1,2):288 (1,2,1):336 (1,2,2):368 (1,2,3):400 (2,0,2):432 (2,1,1):464
//     (2,1,2):496 (2,1,3):528 (2,2,0):560 (2,2,1):592 (2,2,2):624 (2,2,3):656
//   keep bases: l0->0, l1->64, l2->112
//
// 32 threads per row. Thread i handles:
//   LIGHT channel j=32+i : l0 always; l1 paths iff i<16 (l1 channels 32..47).
//   HEAVY channel i      : full l0+l1+l2 path set.
// Every warp has identical work (perfect balance); each output element has a
// unique writer; no shared memory, no barriers. All global accesses are
// sector-coalesced (lane-consecutive small contiguous chunks).
// ============================================================================

#define TPB 256
#define ROWSPB (TPB / 32)
#define DIN 368
#define DOUT 672

__global__ void __launch_bounds__(TPB) selfmix_kernel(
    const float* __restrict__ x, const float* __restrict__ keepc,
    const float* __restrict__ mixc, float* __restrict__ out, int n)
{
    int row = blockIdx.x * ROWSPB + (threadIdx.x >> 5);
    if (row >= n) return;
    int i = threadIdx.x & 31;
    int j = 32 + i;

    const float* xr = x + (long long)row * DIN;
    float* orow = out + (long long)row * DOUT;

    constexpr float S011 = (float)exch_sign<0, 1, 1>();
    constexpr float S022 = (float)exch_sign<0, 2, 2>();
    constexpr float S121 = (float)exch_sign<1, 2, 1>();
    constexpr float S122 = (float)exch_sign<1, 2, 2>();
    constexpr float S123 = (float)exch_sign<1, 2, 3>();

    // ---------------- LIGHT phase: channel j = 32+i ----------------
    {
        float s2[1] = { xr[j] };
        float o0b[1];
        o0b[0] = s2[0] * keepc[j];
        acc_path<0, 0, 0>(0.5f * mixc[j], s2, s2, o0b);

        if (i < 16) {  // l1 channels 32..47
            float u2[3];
#pragma unroll
            for (int m = 0; m < 3; ++m) u2[m] = xr[64 + 3 * j + m];
            float o1b[3];
            float kc = keepc[64 + j];
#pragma unroll
            for (int m = 0; m < 3; ++m) o1b[m] = u2[m] * kc;

            float s011 = 0.5f * (mixc[64 + j] + S011 * mixc[144 + j]);
            acc_path<0, 1, 1>(s011, s2, u2, o1b);
            acc_sym<1, 0>(0.5f * mixc[192 + j], u2, o0b);

            float o2b[5];
#pragma unroll
            for (int m = 0; m < 5; ++m) o2b[m] = 0.0f;
            acc_sym<1, 2>(0.5f * mixc[288 + j], u2, o2b);

#pragma unroll
            for (int m = 0; m < 3; ++m) orow[64 + 3 * j + m] = o1b[m];
#pragma unroll
            for (int m = 0; m < 5; ++m) orow[208 + 5 * j + m] = o2b[m];
        }
        orow[j] = o0b[0];
    }

    // ---------------- HEAVY phase: channel i ----------------
    {
        float s[1] = { xr[i] };
        float u[3];
#pragma unroll
        for (int m = 0; m < 3; ++m) u[m] = xr[64 + 3 * i + m];
        float w[5];
#pragma unroll
        for (int m = 0; m < 5; ++m) w[m] = xr[208 + 5 * i + m];

        float o0[1];
        o0[0] = s[0] * keepc[i];
        acc_path<0, 0, 0>(0.5f * mixc[i], s, s, o0);

        float o1[3];
        float kc1 = keepc[64 + i];
#pragma unroll
        for (int m = 0; m < 3; ++m) o1[m] = u[m] * kc1;

        float o2[5];
        float kc2 = keepc[112 + i];
#pragma unroll
        for (int m = 0; m < 5; ++m) o2[m] = w[m] * kc2;

        float o3[7];
#pragma unroll
        for (int m = 0; m < 7; ++m) o3[m] = 0.0f;

        // fused mirror pairs + symmetric self paths
        acc_path<0, 1, 1>(0.5f * (mixc[64 + i] + S011 * mixc[144 + i]), s, u, o1);
        acc_sym<1, 0>(0.5f * mixc[192 + i], u, o0);
        acc_sym<1, 1>(0.5f * mixc[240 + i], u, o1);   // compile-time dead
        acc_sym<1, 2>(0.5f * mixc[288 + i], u, o2);

        acc_path<0, 2, 2>(0.5f * (mixc[112 + i] + S022 * mixc[432 + i]), s, w, o2);
        acc_path<1, 2, 1>(0.5f * (mixc[336 + i] + S121 * mixc[464 + i]), u, w, o1);
        acc_path<1, 2, 2>(0.5f * (mixc[368 + i] + S122 * mixc[496 + i]), u, w, o2);
        acc_path<1, 2, 3>(0.5f * (mixc[400 + i] + S123 * mixc[528 + i]), u, w, o3);

        acc_sym<2, 0>(0.5f * mixc[560 + i], w, o0);
        acc_sym<2, 1>(0.5f * mixc[592 + i], w, o1);   // dead
        acc_sym<2, 2>(0.5f * mixc[624 + i], w, o2);
        acc_sym<2, 3>(0.5f * mixc[656 + i], w, o3);   // dead

        orow[i] = o0[0];
#pragma unroll
        for (int m = 0; m < 3; ++m) orow[64 + 3 * i + m] = o1[m];
#pragma unroll
        for (int m = 0; m < 5; ++m) orow[208 + 5 * i + m] = o2[m];
#pragma unroll
        for (int m = 0; m < 7; ++m) orow[448 + 7 * i + m] = o3[m];
    }
}

// ============================================================================
// Launch
// ============================================================================
extern "C" void kernel_launch(void* const* d_in, const int* in_sizes, int n_in,
                              void* d_out, int out_size) {
    const float* x     = (const float*)d_in[0];   // [N, 368]
    const float* keepc = (const float*)d_in[1];   // [144]
    const float* mixc  = (const float*)d_in[2];   // [688]
    float* out = (float*)d_out;                   // [N, 672]

    int n = in_sizes[0] / DIN;
    int grid = (n + ROWSPB - 1) / ROWSPB;
    selfmix_kernel<<<grid, TPB>>>(x, keepc, mixc, out, n);
}

// round 11
// speedup vs baseline: 1.3116x; 1.3116x over previous
#include <cuda_runtime.h>

// ============================================================================
// Compile-time real Clebsch-Gordan coefficients (constexpr port of reference)
// ============================================================================

__host__ __device__ constexpr double cfact(int n) {
    double r = 1.0;
    for (int k = 2; k <= n; ++k) r *= (double)k;
    return r;
}

__host__ __device__ constexpr double csqrt(double x) {
    if (x <= 0.0) return 0.0;
    double g = x > 1.0 ? x : 1.0;
    for (int it = 0; it < 100; ++it) g = 0.5 * (g + x / g);
    return g;
}

__host__ __device__ constexpr int imax3(int a, int b, int c) { int m = a; if (b > m) m = b; if (c > m) m = c; return m; }
__host__ __device__ constexpr int imin3(int a, int b, int c) { int m = a; if (b < m) m = b; if (c < m) m = c; return m; }
__host__ __device__ constexpr int iabs_(int a) { return a < 0 ? -a : a; }
__host__ __device__ constexpr double dabs_(double a) { return a < 0.0 ? -a : a; }

// Complex Clebsch-Gordan <l1 m1 l2 m2 | l3 m3> via Racah formula
__host__ __device__ constexpr double cg_complex(int l1, int m1, int l2, int m2, int l3, int m3) {
    if (m1 + m2 != m3 || l3 < iabs_(l1 - l2) || l3 > l1 + l2) return 0.0;
    double pre = csqrt((double)(2 * l3 + 1) * cfact(l1 + l2 - l3) * cfact(l1 - l2 + l3) *
                       cfact(-l1 + l2 + l3) / cfact(l1 + l2 + l3 + 1));
    pre *= csqrt(cfact(l1 + m1) * cfact(l1 - m1) * cfact(l2 + m2) * cfact(l2 - m2) *
                 cfact(l3 + m3) * cfact(l3 - m3));
    int kmin = imax3(0, l2 - l3 - m1, l1 - l3 + m2);
    int kmax = imin3(l1 + l2 - l3, l1 - m1, l2 + m2);
    double s = 0.0;
    for (int k = kmin; k <= kmax; ++k) {
        double d = cfact(k) * cfact(l1 + l2 - l3 - k) * cfact(l1 - m1 - k) *
                   cfact(l2 + m2 - k) * cfact(l3 - l2 + m1 + k) * cfact(l3 - l1 - m2 + k);
        s += ((k & 1) ? -1.0 : 1.0) / d;
    }
    return pre * s;
}

template <int L1, int L2, int L3>
struct CGT {
    double v[2 * L1 + 1][2 * L2 + 1][2 * L3 + 1];
};

// Real-basis CG tensor (exact port of reference: .imag if it dominates, else .real)
template <int L1, int L2, int L3>
__host__ __device__ constexpr CGT<L1, L2, L3> make_cg() {
    constexpr int NA = 2 * L1 + 1, NB = 2 * L2 + 1, NC = 2 * L3 + 1;
    const double is2 = 1.0 / csqrt(2.0);

    double Ur[3][7][7] = {};
    double Ui[3][7][7] = {};
    int Ls[3] = {L1, L2, L3};
    for (int t = 0; t < 3; ++t) {
        int l = Ls[t];
        for (int mp = -l; mp <= l; ++mp) {
            int r = mp + l;
            if (mp > 0) {
                Ur[t][r][mp + l]  = ((mp & 1) ? -1.0 : 1.0) * is2;
                Ur[t][r][-mp + l] = is2;
            } else if (mp == 0) {
                Ur[t][r][l] = 1.0;
            } else {
                Ui[t][r][mp + l]  = is2;
                Ui[t][r][-mp + l] = -(((-mp) & 1) ? -1.0 : 1.0) * is2;
            }
        }
    }

    double Cc[7][7][7] = {};
    for (int m = 0; m < NA; ++m)
        for (int n = 0; n < NB; ++n)
            for (int o = 0; o < NC; ++o)
                Cc[m][n][o] = cg_complex(L1, m - L1, L2, n - L2, L3, o - L3);

    double Tre[NA][NB][NC] = {};
    double Tim[NA][NB][NC] = {};
    double maxre = 0.0, maxim = 0.0;
    for (int a = 0; a < NA; ++a)
        for (int b = 0; b < NB; ++b)
            for (int c = 0; c < NC; ++c) {
                double are = 0.0, aim = 0.0;
                for (int m = 0; m < NA; ++m)
                    for (int n = 0; n < NB; ++n) {
                        int o = (m - L1) + (n - L2) + L3;
                        if (o < 0 || o >= NC) continue;
                        double cc = Cc[m][n][o];
                        if (cc == 0.0) continue;
                        double xr = Ur[0][a][m], xi = Ui[0][a][m];
                        double yr = Ur[1][b][n], yi = Ui[1][b][n];
                        double zr = Ur[2][c][o], zi = -Ui[2][c][o];
                        double pr = xr * yr - xi * yi;
                        double pi = xr * yi + xi * yr;
                        double tr = pr * zr - pi * zi;
                        double ti = pr * zi + pi * zr;
                        are += tr * cc;
                        aim += ti * cc;
                    }
                Tre[a][b][c] = are;
                Tim[a][b][c] = aim;
                if (dabs_(are) > maxre) maxre = dabs_(are);
                if (dabs_(aim) > maxim) maxim = dabs_(aim);
            }

    CGT<L1, L2, L3> R = {};
    bool useim = maxim > maxre;
    for (int a = 0; a < NA; ++a)
        for (int b = 0; b < NB; ++b)
            for (int c = 0; c < NC; ++c)
                R.v[a][b][c] = useim ? Tim[a][b][c] : Tre[a][b][c];
    return R;
}

// Exchange sign sigma s.t. T(L2,L1,L3)[b][a][c] == sigma * T(L1,L2,L3)[a][b][c]
template <int L1, int L2, int L3>
__host__ __device__ constexpr double exch_sign() {
    CGT<L1, L2, L3> A = make_cg<L1, L2, L3>();
    CGT<L2, L1, L3> B = make_cg<L2, L1, L3>();
    for (int a = 0; a < 2 * L1 + 1; ++a)
        for (int b = 0; b < 2 * L2 + 1; ++b)
            for (int c = 0; c < 2 * L3 + 1; ++c)
                if (dabs_(A.v[a][b][c]) > 1e-9)
                    return B.v[b][a][c] / A.v[a][b][c];
    return 0.0;
}

// Does the symmetrized (self-coupling) tensor have any nonzero?
template <int L, int L3>
__host__ __device__ constexpr bool sym_any() {
    CGT<L, L, L3> T = make_cg<L, L, L3>();
    for (int a = 0; a < 2 * L + 1; ++a)
        for (int b = a; b < 2 * L + 1; ++b)
            for (int c = 0; c < 2 * L3 + 1; ++c) {
                double w = (a == b) ? T.v[a][b][c] : (T.v[a][b][c] + T.v[b][a][c]);
                if (dabs_(w) > 1e-12) return true;
            }
    return false;
}

// ============================================================================
// Contractions. CG weights are compile-time constants; ~zero terms are DCE'd,
// surviving terms become FFMA with immediate multipliers.
// ============================================================================

template <int L1, int L2, int L3>
__device__ __forceinline__ void acc_path(float scale, const float* u, const float* v, float* o) {
    constexpr CGT<L1, L2, L3> T = make_cg<L1, L2, L3>();
    float tmp[2 * L3 + 1];
#pragma unroll
    for (int c = 0; c < 2 * L3 + 1; ++c) tmp[c] = 0.0f;
#pragma unroll
    for (int a = 0; a < 2 * L1 + 1; ++a) {
#pragma unroll
        for (int b = 0; b < 2 * L2 + 1; ++b) {
            float p = u[a] * v[b];
#pragma unroll
            for (int c = 0; c < 2 * L3 + 1; ++c) {
                constexpr double EPS = 1e-12;
                double wd = T.v[a][b][c];
                if (wd > EPS || wd < -EPS) tmp[c] = fmaf((float)wd, p, tmp[c]);
            }
        }
    }
#pragma unroll
    for (int c = 0; c < 2 * L3 + 1; ++c) o[c] = fmaf(scale, tmp[c], o[c]);
}

// Self-coupling, symmetrized over (a,b): products only for a<=b; fully
// antisymmetric paths drop at compile time.
template <int L, int L3>
__device__ __forceinline__ void acc_sym(float scale, const float* u, float* o) {
    if constexpr (!sym_any<L, L3>()) return;
    constexpr CGT<L, L, L3> T = make_cg<L, L, L3>();
    float tmp[2 * L3 + 1];
#pragma unroll
    for (int c = 0; c < 2 * L3 + 1; ++c) tmp[c] = 0.0f;
#pragma unroll
    for (int a = 0; a < 2 * L + 1; ++a) {
#pragma unroll
        for (int b = a; b < 2 * L + 1; ++b) {
            float p = u[a] * u[b];
#pragma unroll
            for (int c = 0; c < 2 * L3 + 1; ++c) {
                constexpr double EPS = 1e-12;
                double wd = (a == b) ? T.v[a][b][c] : (T.v[a][b][c] + T.v[b][a][c]);
                if (wd > EPS || wd < -EPS) tmp[c] = fmaf((float)wd, p, tmp[c]);
            }
        }
    }
#pragma unroll
    for (int c = 0; c < 2 * L3 + 1; ++c) o[c] = fmaf(scale, tmp[c], o[c]);
}

// ============================================================================
// Kernel. Layout facts (METADATA=[64,48,32], MAX_L=3):
//   OFF_IN = {0,64,208}, DIM_IN=368; OFF_OUT={0,64,208,448}, DIM_OUT=672
//   (MD_OV={64,48,48,32}: l2 out block has 48 channels; 32..47 fed only by
//    path (1,1,2); keep-l2 covers channels 0..31 only)
//   mix base offsets (PATHS order):
//     (0,0,0):0 (0,1,1):64 (0,2,2):112 (1,0,1):144 (1,1,0):192 (1,1,1):240
//     (1,1,2):288 (1,2,1):336 (1,2,2):368 (1,2,3):400 (2,0,2):432 (2,1,1):464
//     (2,1,2):496 (2,1,3):528 (2,2,0):560 (2,2,1):592 (2,2,2):624 (2,2,3):656
//   keep bases: l0->0, l1->64, l2->112
//
// Structure: R5 float4 smem staging (coalesced global I/O) + R6 balanced
// layout: 32 threads/row, thread i handles HEAVY channel i (full path set)
// and LIGHT channel 32+i (l0 always; l1 iff i<16). All warps do identical
// work; each output element has a unique writer; no atomics.
// ============================================================================

#define TPB 256
#define ROWSPB (TPB / 32)    // 8 rows per block
#define DIN 368
#define DOUT 672

__global__ void __launch_bounds__(TPB) selfmix_kernel(
    const float* __restrict__ x, const float* __restrict__ keepc,
    const float* __restrict__ mixc, float* __restrict__ out, int n)
{
    __shared__ float4 xs4[ROWSPB * DIN / 4];    // 11776 B
    __shared__ float4 os4[ROWSPB * DOUT / 4];   // 21504 B
    float* xs = (float*)xs4;
    float* os = (float*)os4;

    int n0 = blockIdx.x * ROWSPB;
    int nr = n - n0;
    if (nr > ROWSPB) nr = ROWSPB;

    // --- staged, vectorized input load (rows are 16B-aligned: 368*4=1472B) ---
    if (nr == ROWSPB) {
        const float4* xb4 = (const float4*)(x + (long long)n0 * DIN);
#pragma unroll
        for (int t = threadIdx.x; t < ROWSPB * DIN / 4; t += TPB) xs4[t] = xb4[t];
    } else {
        const float* xb = x + (long long)n0 * DIN;
        for (int t = threadIdx.x; t < nr * DIN; t += TPB) xs[t] = xb[t];
    }
    __syncthreads();

    int r = threadIdx.x >> 5;   // row within block (0..7)
    int i = threadIdx.x & 31;   // lane = heavy channel
    int j = 32 + i;             // light channel

    if (r < nr) {
        const float* xr = xs + r * DIN;
        float* orow = os + r * DOUT;

        constexpr float S011 = (float)exch_sign<0, 1, 1>();
        constexpr float S022 = (float)exch_sign<0, 2, 2>();
        constexpr float S121 = (float)exch_sign<1, 2, 1>();
        constexpr float S122 = (float)exch_sign<1, 2, 2>();
        constexpr float S123 = (float)exch_sign<1, 2, 3>();

        // ---------------- LIGHT phase: channel j = 32+i ----------------
        {
            float s2[1] = { xr[j] };
            float o0b[1];
            o0b[0] = s2[0] * keepc[j];
            acc_path<0, 0, 0>(0.5f * mixc[j], s2, s2, o0b);

            if (i < 16) {  // l1 channels 32..47
                float u2[3];
#pragma unroll
                for (int m = 0; m < 3; ++m) u2[m] = xr[64 + 3 * j + m];
                float o1b[3];
                float kc = keepc[64 + j];
#pragma unroll
                for (int m = 0; m < 3; ++m) o1b[m] = u2[m] * kc;

                float s011 = 0.5f * (mixc[64 + j] + S011 * mixc[144 + j]);
                acc_path<0, 1, 1>(s011, s2, u2, o1b);
                acc_sym<1, 0>(0.5f * mixc[192 + j], u2, o0b);

                float o2b[5];
#pragma unroll
                for (int m = 0; m < 5; ++m) o2b[m] = 0.0f;
                acc_sym<1, 2>(0.5f * mixc[288 + j], u2, o2b);

#pragma unroll
                for (int m = 0; m < 3; ++m) orow[64 + 3 * j + m] = o1b[m];
#pragma unroll
                for (int m = 0; m < 5; ++m) orow[208 + 5 * j + m] = o2b[m];
            }
            orow[j] = o0b[0];
        }

        // ---------------- HEAVY phase: channel i ----------------
        {
            float s[1] = { xr[i] };
            float u[3];
#pragma unroll
            for (int m = 0; m < 3; ++m) u[m] = xr[64 + 3 * i + m];
            float w[5];
#pragma unroll
            for (int m = 0; m < 5; ++m) w[m] = xr[208 + 5 * i + m];

            float o0[1];
            o0[0] = s[0] * keepc[i];
            acc_path<0, 0, 0>(0.5f * mixc[i], s, s, o0);

            float o1[3];
            float kc1 = keepc[64 + i];
#pragma unroll
            for (int m = 0; m < 3; ++m) o1[m] = u[m] * kc1;

            float o2[5];
            float kc2 = keepc[112 + i];
#pragma unroll
            for (int m = 0; m < 5; ++m) o2[m] = w[m] * kc2;

            float o3[7];
#pragma unroll
            for (int m = 0; m < 7; ++m) o3[m] = 0.0f;

            // fused mirror pairs + symmetric self paths
            acc_path<0, 1, 1>(0.5f * (mixc[64 + i] + S011 * mixc[144 + i]), s, u, o1);
            acc_sym<1, 0>(0.5f * mixc[192 + i], u, o0);
            acc_sym<1, 1>(0.5f * mixc[240 + i], u, o1);   // compile-time dead
            acc_sym<1, 2>(0.5f * mixc[288 + i], u, o2);

            acc_path<0, 2, 2>(0.5f * (mixc[112 + i] + S022 * mixc[432 + i]), s, w, o2);
            acc_path<1, 2, 1>(0.5f * (mixc[336 + i] + S121 * mixc[464 + i]), u, w, o1);
            acc_path<1, 2, 2>(0.5f * (mixc[368 + i] + S122 * mixc[496 + i]), u, w, o2);
            acc_path<1, 2, 3>(0.5f * (mixc[400 + i] + S123 * mixc[528 + i]), u, w, o3);

            acc_sym<2, 0>(0.5f * mixc[560 + i], w, o0);
            acc_sym<2, 1>(0.5f * mixc[592 + i], w, o1);   // dead
            acc_sym<2, 2>(0.5f * mixc[624 + i], w, o2);
            acc_sym<2, 3>(0.5f * mixc[656 + i], w, o3);   // dead

            orow[i] = o0[0];
#pragma unroll
            for (int m = 0; m < 3; ++m) orow[64 + 3 * i + m] = o1[m];
#pragma unroll
            for (int m = 0; m < 5; ++m) orow[208 + 5 * i + m] = o2[m];
#pragma unroll
            for (int m = 0; m < 7; ++m) orow[448 + 7 * i + m] = o3[m];
        }
    }
    __syncthreads();

    // --- staged, vectorized output store (672*4=2688B rows, 16B-aligned) ---
    if (nr == ROWSPB) {
        float4* ob4 = (float4*)(out + (long long)n0 * DOUT);
#pragma unroll
        for (int t = threadIdx.x; t < ROWSPB * DOUT / 4; t += TPB) ob4[t] = os4[t];
    } else {
        float* ob = out + (long long)n0 * DOUT;
        for (int t = threadIdx.x; t < nr * DOUT; t += TPB) ob[t] = os[t];
    }
}

// ============================================================================
// Launch
// ============================================================================
extern "C" void kernel_launch(void* const* d_in, const int* in_sizes, int n_in,
                              void* d_out, int out_size) {
    const float* x     = (const float*)d_in[0];   // [N, 368]
    const float* keepc = (const float*)d_in[1];   // [144]
    const float* mixc  = (const float*)d_in[2];   // [688]
    float* out = (float*)d_out;                   // [N, 672]

    int n = in_sizes[0] / DIN;
    int grid = (n + ROWSPB - 1) / ROWSPB;
    selfmix_kernel<<<grid, TPB>>>(x, keepc, mixc, out, n);
}

// round 13
// speedup vs baseline: 1.5588x; 1.1885x over previous
#include <cuda_runtime.h>

// ============================================================================
// Compile-time real Clebsch-Gordan coefficients (constexpr port of reference)
// ============================================================================

__host__ __device__ constexpr double cfact(int n) {
    double r = 1.0;
    for (int k = 2; k <= n; ++k) r *= (double)k;
    return r;
}

__host__ __device__ constexpr double csqrt(double x) {
    if (x <= 0.0) return 0.0;
    double g = x > 1.0 ? x : 1.0;
    for (int it = 0; it < 100; ++it) g = 0.5 * (g + x / g);
    return g;
}

__host__ __device__ constexpr int imax3(int a, int b, int c) { int m = a; if (b > m) m = b; if (c > m) m = c; return m; }
__host__ __device__ constexpr int imin3(int a, int b, int c) { int m = a; if (b < m) m = b; if (c < m) m = c; return m; }
__host__ __device__ constexpr int iabs_(int a) { return a < 0 ? -a : a; }
__host__ __device__ constexpr double dabs_(double a) { return a < 0.0 ? -a : a; }

// Complex Clebsch-Gordan <l1 m1 l2 m2 | l3 m3> via Racah formula
__host__ __device__ constexpr double cg_complex(int l1, int m1, int l2, int m2, int l3, int m3) {
    if (m1 + m2 != m3 || l3 < iabs_(l1 - l2) || l3 > l1 + l2) return 0.0;
    double pre = csqrt((double)(2 * l3 + 1) * cfact(l1 + l2 - l3) * cfact(l1 - l2 + l3) *
                       cfact(-l1 + l2 + l3) / cfact(l1 + l2 + l3 + 1));
    pre *= csqrt(cfact(l1 + m1) * cfact(l1 - m1) * cfact(l2 + m2) * cfact(l2 - m2) *
                 cfact(l3 + m3) * cfact(l3 - m3));
    int kmin = imax3(0, l2 - l3 - m1, l1 - l3 + m2);
    int kmax = imin3(l1 + l2 - l3, l1 - m1, l2 + m2);
    double s = 0.0;
    for (int k = kmin; k <= kmax; ++k) {
        double d = cfact(k) * cfact(l1 + l2 - l3 - k) * cfact(l1 - m1 - k) *
                   cfact(l2 + m2 - k) * cfact(l3 - l2 + m1 + k) * cfact(l3 - l1 - m2 + k);
        s += ((k & 1) ? -1.0 : 1.0) / d;
    }
    return pre * s;
}

template <int L1, int L2, int L3>
struct CGT {
    double v[2 * L1 + 1][2 * L2 + 1][2 * L3 + 1];
};

// Real-basis CG tensor (exact port of reference: .imag if it dominates, else .real)
template <int L1, int L2, int L3>
__host__ __device__ constexpr CGT<L1, L2, L3> make_cg() {
    constexpr int NA = 2 * L1 + 1, NB = 2 * L2 + 1, NC = 2 * L3 + 1;
    const double is2 = 1.0 / csqrt(2.0);

    double Ur[3][7][7] = {};
    double Ui[3][7][7] = {};
    int Ls[3] = {L1, L2, L3};
    for (int t = 0; t < 3; ++t) {
        int l = Ls[t];
        for (int mp = -l; mp <= l; ++mp) {
            int r = mp + l;
            if (mp > 0) {
                Ur[t][r][mp + l]  = ((mp & 1) ? -1.0 : 1.0) * is2;
                Ur[t][r][-mp + l] = is2;
            } else if (mp == 0) {
                Ur[t][r][l] = 1.0;
            } else {
                Ui[t][r][mp + l]  = is2;
                Ui[t][r][-mp + l] = -(((-mp) & 1) ? -1.0 : 1.0) * is2;
            }
        }
    }

    double Cc[7][7][7] = {};
    for (int m = 0; m < NA; ++m)
        for (int n = 0; n < NB; ++n)
            for (int o = 0; o < NC; ++o)
                Cc[m][n][o] = cg_complex(L1, m - L1, L2, n - L2, L3, o - L3);

    double Tre[NA][NB][NC] = {};
    double Tim[NA][NB][NC] = {};
    double maxre = 0.0, maxim = 0.0;
    for (int a = 0; a < NA; ++a)
        for (int b = 0; b < NB; ++b)
            for (int c = 0; c < NC; ++c) {
                double are = 0.0, aim = 0.0;
                for (int m = 0; m < NA; ++m)
                    for (int n = 0; n < NB; ++n) {
                        int o = (m - L1) + (n - L2) + L3;
                        if (o < 0 || o >= NC) continue;
                        double cc = Cc[m][n][o];
                        if (cc == 0.0) continue;
                        double xr = Ur[0][a][m], xi = Ui[0][a][m];
                        double yr = Ur[1][b][n], yi = Ui[1][b][n];
                        double zr = Ur[2][c][o], zi = -Ui[2][c][o];
                        double pr = xr * yr - xi * yi;
                        double pi = xr * yi + xi * yr;
                        double tr = pr * zr - pi * zi;
                        double ti = pr * zi + pi * zr;
                        are += tr * cc;
                        aim += ti * cc;
                    }
                Tre[a][b][c] = are;
                Tim[a][b][c] = aim;
                if (dabs_(are) > maxre) maxre = dabs_(are);
                if (dabs_(aim) > maxim) maxim = dabs_(aim);
            }

    CGT<L1, L2, L3> R = {};
    bool useim = maxim > maxre;
    for (int a = 0; a < NA; ++a)
        for (int b = 0; b < NB; ++b)
            for (int c = 0; c < NC; ++c)
                R.v[a][b][c] = useim ? Tim[a][b][c] : Tre[a][b][c];
    return R;
}

// Exchange sign sigma s.t. T(L2,L1,L3)[b][a][c] == sigma * T(L1,L2,L3)[a][b][c]
template <int L1, int L2, int L3>
__host__ __device__ constexpr double exch_sign() {
    CGT<L1, L2, L3> A = make_cg<L1, L2, L3>();
    CGT<L2, L1, L3> B = make_cg<L2, L1, L3>();
    for (int a = 0; a < 2 * L1 + 1; ++a)
        for (int b = 0; b < 2 * L2 + 1; ++b)
            for (int c = 0; c < 2 * L3 + 1; ++c)
                if (dabs_(A.v[a][b][c]) > 1e-9)
                    return B.v[b][a][c] / A.v[a][b][c];
    return 0.0;
}

// Does the symmetrized (self-coupling) tensor have any nonzero?
template <int L, int L3>
__host__ __device__ constexpr bool sym_any() {
    CGT<L, L, L3> T = make_cg<L, L, L3>();
    for (int a = 0; a < 2 * L + 1; ++a)
        for (int b = a; b < 2 * L + 1; ++b)
            for (int c = 0; c < 2 * L3 + 1; ++c) {
                double w = (a == b) ? T.v[a][b][c] : (T.v[a][b][c] + T.v[b][a][c]);
                if (dabs_(w) > 1e-12) return true;
            }
    return false;
}

// ============================================================================
// Contractions. CG weights are compile-time constants; ~zero terms are DCE'd,
// surviving terms become FFMA with immediate multipliers.
// ============================================================================

template <int L1, int L2, int L3>
__device__ __forceinline__ void acc_path(float scale, const float* u, const float* v, float* o) {
    constexpr CGT<L1, L2, L3> T = make_cg<L1, L2, L3>();
    float tmp[2 * L3 + 1];
#pragma unroll
    for (int c = 0; c < 2 * L3 + 1; ++c) tmp[c] = 0.0f;
#pragma unroll
    for (int a = 0; a < 2 * L1 + 1; ++a) {
#pragma unroll
        for (int b = 0; b < 2 * L2 + 1; ++b) {
            float p = u[a] * v[b];
#pragma unroll
            for (int c = 0; c < 2 * L3 + 1; ++c) {
                constexpr double EPS = 1e-12;
                double wd = T.v[a][b][c];
                if (wd > EPS || wd < -EPS) tmp[c] = fmaf((float)wd, p, tmp[c]);
            }
        }
    }
#pragma unroll
    for (int c = 0; c < 2 * L3 + 1; ++c) o[c] = fmaf(scale, tmp[c], o[c]);
}

// Self-coupling, symmetrized over (a,b): products only for a<=b; fully
// antisymmetric paths drop at compile time.
template <int L, int L3>
__device__ __forceinline__ void acc_sym(float scale, const float* u, float* o) {
    if constexpr (!sym_any<L, L3>()) return;
    constexpr CGT<L, L, L3> T = make_cg<L, L, L3>();
    float tmp[2 * L3 + 1];
#pragma unroll
    for (int c = 0; c < 2 * L3 + 1; ++c) tmp[c] = 0.0f;
#pragma unroll
    for (int a = 0; a < 2 * L + 1; ++a) {
#pragma unroll
        for (int b = a; b < 2 * L + 1; ++b) {
            float p = u[a] * u[b];
#pragma unroll
            for (int c = 0; c < 2 * L3 + 1; ++c) {
                constexpr double EPS = 1e-12;
                double wd = (a == b) ? T.v[a][b][c] : (T.v[a][b][c] + T.v[b][a][c]);
                if (wd > EPS || wd < -EPS) tmp[c] = fmaf((float)wd, p, tmp[c]);
            }
        }
    }
#pragma unroll
    for (int c = 0; c < 2 * L3 + 1; ++c) o[c] = fmaf(scale, tmp[c], o[c]);
}

// ============================================================================
// Kernel. Layout facts (METADATA=[64,48,32], MAX_L=3):
//   OFF_IN = {0,64,208}, DIM_IN=368; OFF_OUT={0,64,208,448}, DIM_OUT=672
//   (MD_OV={64,48,48,32}: l2 out block has 48 channels; 32..47 fed only by
//    path (1,1,2); keep-l2 covers channels 0..31 only)
//   mix base offsets (PATHS order):
//     (0,0,0):0 (0,1,1):64 (0,2,2):112 (1,0,1):144 (1,1,0):192 (1,1,1):240
//     (1,1,2):288 (1,2,1):336 (1,2,2):368 (1,2,3):400 (2,0,2):432 (2,1,1):464
//     (2,1,2):496 (2,1,3):528 (2,2,0):560 (2,2,1):592 (2,2,2):624 (2,2,3):656
//   keep bases: l0->0, l1->64, l2->112
//
// WARP-AUTONOMOUS version: one warp per row with a PRIVATE smem slice.
// Staging in (coalesced float4), compute, staging out (coalesced float4)
// are all intra-warp -> __syncwarp() only, no block barriers. Warps slip
// freely against each other so memory latency is hidden by other warps'
// compute. Thread i handles HEAVY channel i (full path set) and LIGHT
// channel 32+i (l0 always; l1 iff i<16). Unique writer per output element.
// ============================================================================

#define TPB 256
#define WARPS_PB (TPB / 32)   // 8 warps = 8 rows per block
#define DIN 368               // 92 float4
#define DOUT 672              // 168 float4
#define WSLOT (DIN + DOUT)    // 1040 floats = 260 float4 per warp

__global__ void __launch_bounds__(TPB) selfmix_kernel(
    const float* __restrict__ x, const float* __restrict__ keepc,
    const float* __restrict__ mixc, float* __restrict__ out, int n)
{
    __shared__ float4 smem4[WARPS_PB * WSLOT / 4];   // 33280 B

    int w = threadIdx.x >> 5;          // warp id in block
    int lane = threadIdx.x & 31;
    int row = blockIdx.x * WARPS_PB + w;
    if (row >= n) return;

    float4* xw4 = smem4 + w * (WSLOT / 4);          // 92 float4 input slice
    float4* ow4 = xw4 + (DIN / 4);                  // 168 float4 output slice
    float* xr = (float*)xw4;
    float* orow = (float*)ow4;

    // --- warp-private staged input load (row is 16B-aligned: 368*4=1472B) ---
    {
        const float4* xg4 = (const float4*)(x + (long long)row * DIN);
#pragma unroll
        for (int t = lane; t < DIN / 4; t += 32) xw4[t] = xg4[t];
    }
    __syncwarp();

    int i = lane;        // heavy channel
    int j = 32 + i;      // light channel

    constexpr float S011 = (float)exch_sign<0, 1, 1>();
    constexpr float S022 = (float)exch_sign<0, 2, 2>();
    constexpr float S121 = (float)exch_sign<1, 2, 1>();
    constexpr float S122 = (float)exch_sign<1, 2, 2>();
    constexpr float S123 = (float)exch_sign<1, 2, 3>();

    // ---------------- LIGHT phase: channel j = 32+i ----------------
    {
        float s2[1] = { xr[j] };
        float o0b[1];
        o0b[0] = s2[0] * keepc[j];
        acc_path<0, 0, 0>(0.5f * mixc[j], s2, s2, o0b);

        if (i < 16) {  // l1 channels 32..47
            float u2[3];
#pragma unroll
            for (int m = 0; m < 3; ++m) u2[m] = xr[64 + 3 * j + m];
            float o1b[3];
            float kc = keepc[64 + j];
#pragma unroll
            for (int m = 0; m < 3; ++m) o1b[m] = u2[m] * kc;

            float s011 = 0.5f * (mixc[64 + j] + S011 * mixc[144 + j]);
            acc_path<0, 1, 1>(s011, s2, u2, o1b);
            acc_sym<1, 0>(0.5f * mixc[192 + j], u2, o0b);

            float o2b[5];
#pragma unroll
            for (int m = 0; m < 5; ++m) o2b[m] = 0.0f;
            acc_sym<1, 2>(0.5f * mixc[288 + j], u2, o2b);

#pragma unroll
            for (int m = 0; m < 3; ++m) orow[64 + 3 * j + m] = o1b[m];
#pragma unroll
            for (int m = 0; m < 5; ++m) orow[208 + 5 * j + m] = o2b[m];
        }
        orow[j] = o0b[0];
    }

    // ---------------- HEAVY phase: channel i ----------------
    {
        float s[1] = { xr[i] };
        float u[3];
#pragma unroll
        for (int m = 0; m < 3; ++m) u[m] = xr[64 + 3 * i + m];
        float w5[5];
#pragma unroll
        for (int m = 0; m < 5; ++m) w5[m] = xr[208 + 5 * i + m];

        float o0[1];
        o0[0] = s[0] * keepc[i];
        acc_path<0, 0, 0>(0.5f * mixc[i], s, s, o0);

        float o1[3];
        float kc1 = keepc[64 + i];
#pragma unroll
        for (int m = 0; m < 3; ++m) o1[m] = u[m] * kc1;

        float o2[5];
        float kc2 = keepc[112 + i];
#pragma unroll
        for (int m = 0; m < 5; ++m) o2[m] = w5[m] * kc2;

        float o3[7];
#pragma unroll
        for (int m = 0; m < 7; ++m) o3[m] = 0.0f;

        // fused mirror pairs + symmetric self paths
        acc_path<0, 1, 1>(0.5f * (mixc[64 + i] + S011 * mixc[144 + i]), s, u, o1);
        acc_sym<1, 0>(0.5f * mixc[192 + i], u, o0);
        acc_sym<1, 1>(0.5f * mixc[240 + i], u, o1);   // compile-time dead
        acc_sym<1, 2>(0.5f * mixc[288 + i], u, o2);

        acc_path<0, 2, 2>(0.5f * (mixc[112 + i] + S022 * mixc[432 + i]), s, w5, o2);
        acc_path<1, 2, 1>(0.5f * (mixc[336 + i] + S121 * mixc[464 + i]), u, w5, o1);
        acc_path<1, 2, 2>(0.5f * (mixc[368 + i] + S122 * mixc[496 + i]), u, w5, o2);
        acc_path<1, 2, 3>(0.5f * (mixc[400 + i] + S123 * mixc[528 + i]), u, w5, o3);

        acc_sym<2, 0>(0.5f * mixc[560 + i], w5, o0);
        acc_sym<2, 1>(0.5f * mixc[592 + i], w5, o1);   // dead
        acc_sym<2, 2>(0.5f * mixc[624 + i], w5, o2);
        acc_sym<2, 3>(0.5f * mixc[656 + i], w5, o3);   // dead

        orow[i] = o0[0];
#pragma unroll
        for (int m = 0; m < 3; ++m) orow[64 + 3 * i + m] = o1[m];
#pragma unroll
        for (int m = 0; m < 5; ++m) orow[208 + 5 * i + m] = o2[m];
#pragma unroll
        for (int m = 0; m < 7; ++m) orow[448 + 7 * i + m] = o3[m];
    }
    __syncwarp();

    // --- warp-private staged output store (672*4=2688B row, 16B-aligned) ---
    {
        float4* og4 = (float4*)(out + (long long)row * DOUT);
#pragma unroll
        for (int t = lane; t < DOUT / 4; t += 32) og4[t] = ow4[t];
    }
}

// ============================================================================
// Launch
// ============================================================================
extern "C" void kernel_launch(void* const* d_in, const int* in_sizes, int n_in,
                              void* d_out, int out_size) {
    const float* x     = (const float*)d_in[0];   // [N, 368]
    const float* keepc = (const float*)d_in[1];   // [144]
    const float* mixc  = (const float*)d_in[2];   // [688]
    float* out = (float*)d_out;                   // [N, 672]

    int n = in_sizes[0] / DIN;
    int grid = (n + WARPS_PB - 1) / WARPS_PB;
    selfmix_kernel<<<grid, TPB>>>(x, keepc, mixc, out, n);
}